// round 2
// baseline (speedup 1.0000x reference)
#include <cuda_runtime.h>
#include <math.h>

static constexpr int V   = 2048;
static constexpr int VM1 = 2047;
static constexpr float PPROB    = 0.1f;
static constexpr float INV_VM2  = 1.0f / 2046.0f;
static constexpr float LOG_KEEP = -0.10536051565782628f;  // ln(0.9)
static constexpr float LOG_REP  = -9.9262269f;            // ln(0.1/2046)

__global__ __launch_bounds__(256)
void sym_channel_kernel(const float* __restrict__ msgs,
                        const float* __restrict__ logits,
                        const float* __restrict__ noise,
                        float* __restrict__ out,
                        int nrows)
{
    __shared__ float sm_tb[512];     // t of element (i4*4+3), one per float4 chunk
    __shared__ float warp_sums[8];

    const int r   = blockIdx.x;
    const int tid = threadIdx.x;
    const size_t rowoff = (size_t)r * V;
    const size_t N      = (size_t)nrows * V;

    const float4* m4   = reinterpret_cast<const float4*>(msgs + rowoff);
    const float4* l4   = reinterpret_cast<const float4*>(logits + rowoff);
    const float*  nrow = noise + (size_t)r * VM1;

    float4* out_m4  = reinterpret_cast<float4*>(out + rowoff);          // m_noisy
    float4* out_l4  = reinterpret_cast<float4*>(out + N + rowoff);      // logits_noisy
    float4* out_mc4 = reinterpret_cast<float4*>(out + 2 * N + rowoff);  // messages copy
    float4* out_lc4 = reinterpret_cast<float4*>(out + 3 * N + rowoff);  // logits copy

    // ---- front-batch all global loads (max MLP) ----
    float4 mv[2];
    mv[0] = m4[tid];
    mv[1] = m4[tid + 256];
    float4 lv[2];
    lv[0] = l4[tid];
    lv[1] = l4[tid + 256];
    const float l0 = __ldg(logits + rowoff);   // broadcast, 1 sector/row
    float nz[8];
    #pragma unroll
    for (int k = 0; k < 2; k++) {
        int base = (tid + k * 256) * 4;
        #pragma unroll
        for (int j = 0; j < 4; j++) {
            int c = base + j;
            nz[k * 4 + j] = (c < VM1) ? nrow[c] : 1.0f;  // >=P -> no hit
        }
    }

    // ---- verbatim copies ----
    out_mc4[tid]       = mv[0];
    out_mc4[tid + 256] = mv[1];
    out_lc4[tid]       = lv[0];
    out_lc4[tid + 256] = lv[1];

    // ---- hit mask + local masked sum + boundary t to smem ----
    unsigned msk = 0;
    float lsum = 0.0f;
    #pragma unroll
    for (int k = 0; k < 2; k++) {
        const float* mp = &mv[k].x;
        #pragma unroll
        for (int j = 0; j < 4; j++) {
            if (nz[k * 4 + j] < PPROB) {
                msk |= 1u << (k * 4 + j);
                lsum += mp[j];
            }
        }
        sm_tb[tid + k * 256] = ((msk >> (k * 4 + 3)) & 1) ? mp[3] : 0.0f;
    }

    // ---- reduction arrive (barrier comes after the logits work below) ----
    float wsum = lsum;
    #pragma unroll
    for (int off = 16; off > 0; off >>= 1)
        wsum += __shfl_down_sync(0xFFFFFFFFu, wsum, off);
    if ((tid & 31) == 0) warp_sums[tid >> 5] = wsum;

    // ---- logits_noisy: independent of barrier/reduction, hides sync slack ----
    const float e0 = expf(l0);
    #pragma unroll
    for (int k = 0; k < 2; k++) {
        int i4 = tid + k * 256;
        const float* lp = &lv[k].x;
        float4 o;
        float* op = &o.x;
        #pragma unroll
        for (int j = 0; j < 4; j++) {
            int jj = i4 * 4 + j;
            if (jj == 0) { op[j] = l0; continue; }
            float ljv = lp[j];
            float pt = fminf(fmaxf(1.0f - expf(ljv) - e0, 0.0f), 1.0f);
            float a = ljv + LOG_KEEP;
            float b = logf(pt) + LOG_REP;        // logf(0) = -inf is fine
            float mx = fmaxf(a, b);
            float mn = fminf(a, b);
            op[j] = mx + log1pf(expf(mn - mx));  // exp(-inf)=0 -> mx
        }
        out_l4[i4] = o;
    }

    __syncthreads();   // covers warp_sums + sm_tb

    float row_sum = 0.0f;
    #pragma unroll
    for (int w = 0; w < 8; w++) row_sum += warp_sums[w];
    const float add_c = row_sum * INV_VM2;
    const float scale = 1.0f + INV_VM2;

    // ---- m_noisy from registers; only j==0 touches smem ----
    #pragma unroll
    for (int k = 0; k < 2; k++) {
        int i4 = tid + k * 256;
        const float* mp = &mv[k].x;
        float4 o;
        float* op = &o.x;
        #pragma unroll
        for (int j = 0; j < 4; j++) {
            float tprev;
            if (j == 0) {
                tprev = (i4 == 0) ? 0.0f : sm_tb[i4 - 1];
            } else {
                tprev = ((msk >> (k * 4 + j - 1)) & 1) ? mp[j - 1] : 0.0f;
            }
            float val = mp[j];
            if (i4 * 4 + j > 0) val += add_c - tprev * scale;
            op[j] = val;
        }
        out_m4[i4] = o;
    }
}

extern "C" void kernel_launch(void* const* d_in, const int* in_sizes, int n_in,
                              void* d_out, int out_size)
{
    const float* msgs   = (const float*)d_in[0];
    const float* logits = (const float*)d_in[1];
    const float* noise  = (const float*)d_in[2];
    float* out = (float*)d_out;
    int nrows = in_sizes[0] / V;   // 16384
    sym_channel_kernel<<<nrows, 256>>>(msgs, logits, noise, out, nrows);
}

// round 3
// speedup vs baseline: 1.0142x; 1.0142x over previous
#include <cuda_runtime.h>
#include <math.h>

static constexpr int V   = 2048;
static constexpr int VM1 = 2047;
static constexpr float PPROB    = 0.1f;
static constexpr float INV_VM2  = 1.0f / 2046.0f;
static constexpr float LOG_KEEP = -0.10536051565782628f;  // ln(0.9)
static constexpr float LOG_REP  = -9.9262269f;            // ln(0.1/2046)

__global__ __launch_bounds__(256)
void sym_channel_kernel(const float* __restrict__ msgs,
                        const float* __restrict__ logits,
                        const float* __restrict__ noise,
                        float* __restrict__ out,
                        int nrows)
{
    __shared__ float sm_tb[512];     // t of element (i4*4+3), one per float4 chunk
    __shared__ float warp_sums[8];

    const int r   = blockIdx.x;
    const int tid = threadIdx.x;
    const size_t rowoff = (size_t)r * V;
    const size_t N      = (size_t)nrows * V;

    const float4* m4   = reinterpret_cast<const float4*>(msgs + rowoff);
    const float4* l4   = reinterpret_cast<const float4*>(logits + rowoff);
    const float*  nrow = noise + (size_t)r * VM1;

    float4* out_m4  = reinterpret_cast<float4*>(out + rowoff);          // m_noisy
    float4* out_l4  = reinterpret_cast<float4*>(out + N + rowoff);      // logits_noisy
    float4* out_mc4 = reinterpret_cast<float4*>(out + 2 * N + rowoff);  // messages copy
    float4* out_lc4 = reinterpret_cast<float4*>(out + 3 * N + rowoff);  // logits copy

    // ---- front-batch all global loads, streaming (evict-first) policy ----
    float4 mv[2];
    mv[0] = __ldcs(&m4[tid]);
    mv[1] = __ldcs(&m4[tid + 256]);
    float4 lv[2];
    lv[0] = __ldcs(&l4[tid]);
    lv[1] = __ldcs(&l4[tid + 256]);
    const float l0 = __ldg(logits + rowoff);   // broadcast, 1 sector/row
    float nz[8];
    #pragma unroll
    for (int k = 0; k < 2; k++) {
        int base = (tid + k * 256) * 4;
        #pragma unroll
        for (int j = 0; j < 4; j++) {
            int c = base + j;
            nz[k * 4 + j] = (c < VM1) ? __ldcs(&nrow[c]) : 1.0f;  // >=P -> no hit
        }
    }

    // ---- verbatim copies (streaming stores) ----
    __stcs(&out_mc4[tid],       mv[0]);
    __stcs(&out_mc4[tid + 256], mv[1]);
    __stcs(&out_lc4[tid],       lv[0]);
    __stcs(&out_lc4[tid + 256], lv[1]);

    // ---- hit mask + local masked sum + boundary t to smem ----
    unsigned msk = 0;
    float lsum = 0.0f;
    #pragma unroll
    for (int k = 0; k < 2; k++) {
        const float* mp = &mv[k].x;
        #pragma unroll
        for (int j = 0; j < 4; j++) {
            if (nz[k * 4 + j] < PPROB) {
                msk |= 1u << (k * 4 + j);
                lsum += mp[j];
            }
        }
        sm_tb[tid + k * 256] = ((msk >> (k * 4 + 3)) & 1) ? mp[3] : 0.0f;
    }

    // ---- reduction arrive (barrier comes after the logits work below) ----
    float wsum = lsum;
    #pragma unroll
    for (int off = 16; off > 0; off >>= 1)
        wsum += __shfl_down_sync(0xFFFFFFFFu, wsum, off);
    if ((tid & 31) == 0) warp_sums[tid >> 5] = wsum;

    // ---- logits_noisy: independent of barrier/reduction, hides sync slack ----
    const float e0 = expf(l0);
    #pragma unroll
    for (int k = 0; k < 2; k++) {
        int i4 = tid + k * 256;
        const float* lp = &lv[k].x;
        float4 o;
        float* op = &o.x;
        #pragma unroll
        for (int j = 0; j < 4; j++) {
            int jj = i4 * 4 + j;
            if (jj == 0) { op[j] = l0; continue; }
            float ljv = lp[j];
            float pt = fminf(fmaxf(1.0f - expf(ljv) - e0, 0.0f), 1.0f);
            float a = ljv + LOG_KEEP;
            float b = logf(pt) + LOG_REP;        // logf(0) = -inf is fine
            float mx = fmaxf(a, b);
            float mn = fminf(a, b);
            op[j] = mx + log1pf(expf(mn - mx));  // exp(-inf)=0 -> mx
        }
        __stcs(&out_l4[i4], o);
    }

    __syncthreads();   // covers warp_sums + sm_tb

    float row_sum = 0.0f;
    #pragma unroll
    for (int w = 0; w < 8; w++) row_sum += warp_sums[w];
    const float add_c = row_sum * INV_VM2;
    const float scale = 1.0f + INV_VM2;

    // ---- m_noisy from registers; only j==0 touches smem ----
    #pragma unroll
    for (int k = 0; k < 2; k++) {
        int i4 = tid + k * 256;
        const float* mp = &mv[k].x;
        float4 o;
        float* op = &o.x;
        #pragma unroll
        for (int j = 0; j < 4; j++) {
            float tprev;
            if (j == 0) {
                tprev = (i4 == 0) ? 0.0f : sm_tb[i4 - 1];
            } else {
                tprev = ((msk >> (k * 4 + j - 1)) & 1) ? mp[j - 1] : 0.0f;
            }
            float val = mp[j];
            if (i4 * 4 + j > 0) val += add_c - tprev * scale;
            op[j] = val;
        }
        __stcs(&out_m4[i4], o);
    }
}

extern "C" void kernel_launch(void* const* d_in, const int* in_sizes, int n_in,
                              void* d_out, int out_size)
{
    const float* msgs   = (const float*)d_in[0];
    const float* logits = (const float*)d_in[1];
    const float* noise  = (const float*)d_in[2];
    float* out = (float*)d_out;
    int nrows = in_sizes[0] / V;   // 16384
    sym_channel_kernel<<<nrows, 256>>>(msgs, logits, noise, out, nrows);
}